// round 16
// baseline (speedup 1.0000x reference)
#include <cuda_runtime.h>
#include <cuda_bf16.h>
#include <math.h>
#include <stdint.h>

#define KDIM 4608
#define N0   512
#define WDC  0.0005f

// output layout (floats): new_e, new_s, L, hn, cn
#define O_E 0
#define O_S 16777216
#define O_L 19136512
#define O_H 40370176
#define O_C 40554496

// ---------------- scratch ----------------
__device__ __align__(256) float g_M[KDIM * N0];
__device__ __align__(256) float g_G[KDIM * N0];      // Mg -> G -> Q3
__device__ __align__(256) float g_A[KDIM * N0];      // LG -> A -> Q1 -> Q2
__device__ __align__(256) float g_S[N0 * N0];        // Gram -> chol L (lower)
__device__ __align__(256) float g_Sym[N0 * N0];      // Sym / P-scratch for trinv
__device__ __align__(256) float g_part[4 * N0 * N0]; // split-K partials / Linv
__device__ __align__(256) float g_x[KDIM];
__device__ __align__(256) float g_lraw[KDIM];
__device__ float g_mean;
__device__ __align__(256) __nv_bfloat16 g_Lhi[(size_t)KDIM * KDIM];
__device__ __align__(256) __nv_bfloat16 g_Llo[(size_t)KDIM * KDIM];
__device__ __align__(256) __nv_bfloat16 g_Gthi[(size_t)N0 * KDIM];  // G^T; later Q1 rows
__device__ __align__(256) __nv_bfloat16 g_Gtlo[(size_t)N0 * KDIM];
__device__ __align__(256) __nv_bfloat16 g_MThi[(size_t)N0 * KDIM];
__device__ __align__(256) __nv_bfloat16 g_MTlo[(size_t)N0 * KDIM];
__device__ __align__(256) __nv_bfloat16 g_XThi[(size_t)N0 * KDIM];
__device__ __align__(256) __nv_bfloat16 g_XTlo[(size_t)N0 * KDIM];
__device__ __align__(256) __nv_bfloat16 g_MRhi[(size_t)KDIM * N0];  // M rows; later Q2 rows
__device__ __align__(256) __nv_bfloat16 g_MRlo[(size_t)KDIM * N0];
__device__ __align__(256) __nv_bfloat16 g_XRhi[(size_t)KDIM * N0];  // A rows
__device__ __align__(256) __nv_bfloat16 g_XRlo[(size_t)KDIM * N0];
__device__ __align__(256) __nv_bfloat16 g_Bophi[N0 * N0];
__device__ __align__(256) __nv_bfloat16 g_Boplo[N0 * N0];

__device__ __forceinline__ float sigf(float z) { return 1.0f / (1.0f + expf(-z)); }

#define MMA16(ACC, AV, BV)                                                       \
    asm volatile("mma.sync.aligned.m16n8k16.row.col.f32.bf16.bf16.f32 "          \
                 "{%0,%1,%2,%3}, {%4,%5,%6,%7}, {%8,%9}, {%0,%1,%2,%3};"         \
                 : "+f"((ACC)[0]), "+f"((ACC)[1]), "+f"((ACC)[2]), "+f"((ACC)[3])\
                 : "r"((AV)[0]), "r"((AV)[1]), "r"((AV)[2]), "r"((AV)[3]),       \
                   "r"((BV)[0]), "r"((BV)[1]))

// ---------------- new_e ----------------
__global__ void k_update_e(const float4* __restrict__ e, const float4* __restrict__ eg,
                           const float* __restrict__ e_lr, float4* __restrict__ out) {
    int i = blockIdx.x * 256 + threadIdx.x;
    float lr = *e_lr;
    float4 a = e[i], g = eg[i];
    float4 r;
    r.x = a.x - lr * (g.x + WDC * a.x);
    r.y = a.y - lr * (g.y + WDC * a.y);
    r.z = a.z - lr * (g.z + WDC * a.z);
    r.w = a.w - lr * (g.w + WDC * a.w);
    out[i] = r;
}

// ---------------- M, Mg ----------------
__global__ void k_make_MMg(const float* __restrict__ s, const float* __restrict__ sg,
                           const float* __restrict__ s_lr) {
    __shared__ float t0[32][33];
    __shared__ float t1[32][33];
    int iB = blockIdx.x * 32, jB = blockIdx.y * 32;
    int tx = threadIdx.x, ty = threadIdx.y;
#pragma unroll
    for (int r = 0; r < 32; r += 8) {
        t0[ty + r][tx] = s [(jB + ty + r) * KDIM + iB + tx];
        t1[ty + r][tx] = sg[(jB + ty + r) * KDIM + iB + tx];
    }
    __syncthreads();
    float nslr = -(*s_lr);
#pragma unroll
    for (int r = 0; r < 32; r += 8) {
        int i = iB + ty + r;
        g_M[i * N0 + jB + tx] = t0[tx][ty + r];
        g_G[i * N0 + jB + tx] = nslr * t1[tx][ty + r];
    }
}

// ---------------- split directly from s/sg (already M^T layout) ----------------
__global__ void k_stsplit(const float4* __restrict__ src, const float* __restrict__ lr,
                          int sel) {
    int gid = blockIdx.x * 256 + threadIdx.x;
    float sc = sel ? -(*lr) : 1.0f;
    float4 v = src[gid];
    v.x *= sc; v.y *= sc; v.z *= sc; v.w *= sc;
    __nv_bfloat162* dh = (__nv_bfloat162*)(sel ? g_XThi : g_MThi);
    __nv_bfloat162* dl = (__nv_bfloat162*)(sel ? g_XTlo : g_MTlo);
    __nv_bfloat16 hx = __float2bfloat16(v.x), hy = __float2bfloat16(v.y);
    __nv_bfloat16 hz = __float2bfloat16(v.z), hw = __float2bfloat16(v.w);
    dh[2 * gid]     = __nv_bfloat162(hx, hy);
    dh[2 * gid + 1] = __nv_bfloat162(hz, hw);
    dl[2 * gid]     = __nv_bfloat162(__float2bfloat16(v.x - __bfloat162float(hx)),
                                     __float2bfloat16(v.y - __bfloat162float(hy)));
    dl[2 * gid + 1] = __nv_bfloat162(__float2bfloat16(v.z - __bfloat162float(hz)),
                                     __float2bfloat16(v.w - __bfloat162float(hw)));
}

// ---------------- fp32 Gram (pass-1 only): C = A^T A split-K ----------------
__global__ void k_gemm_tn() {
    const float* A = g_A;
    __shared__ __align__(16) float As[16][68];
    __shared__ __align__(16) float Bs[16][68];
    int a0 = blockIdx.x * 64, b0 = blockIdx.y * 64;
    int k0 = blockIdx.z * (KDIM / 4);
    int t = threadIdx.x, tx = t & 15, ty = t >> 4;
    int lr = t >> 4, lc = t & 15;
    float acc[4][4] = {};
    for (int kk = 0; kk < KDIM / 4; kk += 16) {
        float4 va = *(const float4*)&A[(k0 + kk + lr) * N0 + a0 + lc * 4];
        float4 vb = *(const float4*)&A[(k0 + kk + lr) * N0 + b0 + lc * 4];
        *(float4*)&As[lr][lc * 4] = va;
        *(float4*)&Bs[lr][lc * 4] = vb;
        __syncthreads();
#pragma unroll
        for (int k = 0; k < 16; k++) {
            float4 av = *(const float4*)&As[k][ty * 4];
            float4 bv = *(const float4*)&Bs[k][tx * 4];
            float a_[4] = {av.x, av.y, av.z, av.w};
            float b_[4] = {bv.x, bv.y, bv.z, bv.w};
#pragma unroll
            for (int u = 0; u < 4; u++)
#pragma unroll
                for (int v = 0; v < 4; v++) acc[u][v] += a_[u] * b_[v];
        }
        __syncthreads();
    }
    float* C = g_part + blockIdx.z * (N0 * N0);
#pragma unroll
    for (int u = 0; u < 4; u++)
#pragma unroll
        for (int v = 0; v < 4; v++)
            C[(a0 + ty * 4 + u) * N0 + (b0 + tx * 4 + v)] = acc[u][v];
}

// ------- reduce split-K + symmetrize; optionally emit Bop split (bmode -1/0/1) -------
__global__ void k_reduce_sym(int dst, int bmode) {
    int idx = blockIdx.x * 512 + threadIdx.x;
    int a = idx >> 9, b = idx & 511;
    float s1 = 0.f, s2 = 0.f;
#pragma unroll
    for (int z = 0; z < 4; z++) {
        s1 += g_part[z * N0 * N0 + idx];
        s2 += g_part[z * N0 * N0 + b * N0 + a];
    }
    float v = 0.5f * (s1 + s2);
    if (dst == 0) g_Sym[idx] = v; else g_S[idx] = v;
    if (bmode >= 0) {
        float bv = v;
        if (bmode == 1)
            bv = (b < a) ? v : ((b == a) ? 0.5f * (v - 1.0f) : 0.0f);
        __nv_bfloat16 h = __float2bfloat16(bv);
        g_Bophi[idx] = h;
        g_Boplo[idx] = __float2bfloat16(bv - __bfloat162float(h));
    }
}

// ---------------- transpose + split: sel 1:A->XT 3:G->Gt ----------------
__global__ void k_tsplit(int sel) {
    __shared__ float tile[32][33];
    const float* src = (sel == 1) ? g_A : g_G;
    __nv_bfloat16* dh = (sel == 3) ? g_Gthi : g_XThi;
    __nv_bfloat16* dl = (sel == 3) ? g_Gtlo : g_XTlo;
    int kB = blockIdx.x * 32, nB = blockIdx.y * 32;
    int tx = threadIdx.x, ty = threadIdx.y;
#pragma unroll
    for (int r = 0; r < 32; r += 8)
        tile[ty + r][tx] = src[(kB + ty + r) * N0 + nB + tx];
    __syncthreads();
#pragma unroll
    for (int r = 0; r < 32; r += 8) {
        float v = tile[tx][ty + r];
        __nv_bfloat16 h = __float2bfloat16(v);
        size_t idx = (size_t)(nB + ty + r) * KDIM + kB + tx;
        dh[idx] = h;
        dl[idx] = __float2bfloat16(v - __bfloat162float(h));
    }
}

// ---------------- row split: M -> MR ----------------
__global__ void k_rsplit() {
    int gid = blockIdx.x * 256 + threadIdx.x;
    const float4* src = (const float4*)g_M;
    __nv_bfloat162* dh = (__nv_bfloat162*)g_MRhi;
    __nv_bfloat162* dl = (__nv_bfloat162*)g_MRlo;
    float4 v = src[gid];
    __nv_bfloat16 hx = __float2bfloat16(v.x), hy = __float2bfloat16(v.y);
    __nv_bfloat16 hz = __float2bfloat16(v.z), hw = __float2bfloat16(v.w);
    dh[2 * gid]     = __nv_bfloat162(hx, hy);
    dh[2 * gid + 1] = __nv_bfloat162(hz, hw);
    dl[2 * gid]     = __nv_bfloat162(__float2bfloat16(v.x - __bfloat162float(hx)),
                                     __float2bfloat16(v.y - __bfloat162float(hy)));
    dl[2 * gid + 1] = __nv_bfloat162(__float2bfloat16(v.z - __bfloat162float(hz)),
                                     __float2bfloat16(v.w - __bfloat162float(hw)));
}

// ---------------- Bop from Linv (g_part, lower-masked) ----------------
__global__ void k_bsplit_linv() {
    int j = blockIdx.x, a = threadIdx.x;
    float v = (a <= j) ? g_part[j * N0 + a] : 0.0f;
    __nv_bfloat16 h = __float2bfloat16(v);
    g_Bophi[j * N0 + a] = h;
    g_Boplo[j * N0 + a] = __float2bfloat16(v - __bfloat162float(h));
}

// ======== 128x128-tile split-bf16 HMMA core (3-term), warp tile 32x64 ========
template <int STRIDE>
__device__ __forceinline__ void mma128(
    const __nv_bfloat16* __restrict__ Ah, const __nv_bfloat16* __restrict__ Al,
    const __nv_bfloat16* __restrict__ Bh, const __nv_bfloat16* __restrict__ Bl,
    int i0, int n0t, int kbeg, int kend, float acc[2][8][4],
    __nv_bfloat16 (*sAh)[40], __nv_bfloat16 (*sAl)[40],
    __nv_bfloat16 (*sBh)[40], __nv_bfloat16 (*sBl)[40]) {
    int t = threadIdx.x, lane = t & 31, wid = t >> 5;
    int wy = wid >> 1, wx = wid & 1;
    int r0 = t >> 2, c0 = (t & 3) * 8;
    int r1 = r0 + 64;
    int gr = lane >> 2, lc2 = (lane & 3) * 2;
    uint4 pAh0 = *(const uint4*)(Ah + (size_t)(i0 + r0) * STRIDE + kbeg + c0);
    uint4 pAh1 = *(const uint4*)(Ah + (size_t)(i0 + r1) * STRIDE + kbeg + c0);
    uint4 pAl0 = *(const uint4*)(Al + (size_t)(i0 + r0) * STRIDE + kbeg + c0);
    uint4 pAl1 = *(const uint4*)(Al + (size_t)(i0 + r1) * STRIDE + kbeg + c0);
    uint4 pBh0 = *(const uint4*)(Bh + (size_t)(n0t + r0) * STRIDE + kbeg + c0);
    uint4 pBh1 = *(const uint4*)(Bh + (size_t)(n0t + r1) * STRIDE + kbeg + c0);
    uint4 pBl0 = *(const uint4*)(Bl + (size_t)(n0t + r0) * STRIDE + kbeg + c0);
    uint4 pBl1 = *(const uint4*)(Bl + (size_t)(n0t + r1) * STRIDE + kbeg + c0);
    for (int k0 = kbeg; k0 < kend; k0 += 32) {
        *(uint4*)&sAh[r0][c0] = pAh0;
        *(uint4*)&sAh[r1][c0] = pAh1;
        *(uint4*)&sAl[r0][c0] = pAl0;
        *(uint4*)&sAl[r1][c0] = pAl1;
        *(uint4*)&sBh[r0][c0] = pBh0;
        *(uint4*)&sBh[r1][c0] = pBh1;
        *(uint4*)&sBl[r0][c0] = pBl0;
        *(uint4*)&sBl[r1][c0] = pBl1;
        __syncthreads();
        if (k0 + 32 < kend) {
            size_t ko = (size_t)(k0 + 32 + c0);
            pAh0 = *(const uint4*)(Ah + (size_t)(i0 + r0) * STRIDE + ko);
            pAh1 = *(const uint4*)(Ah + (size_t)(i0 + r1) * STRIDE + ko);
            pAl0 = *(const uint4*)(Al + (size_t)(i0 + r0) * STRIDE + ko);
            pAl1 = *(const uint4*)(Al + (size_t)(i0 + r1) * STRIDE + ko);
            pBh0 = *(const uint4*)(Bh + (size_t)(n0t + r0) * STRIDE + ko);
            pBh1 = *(const uint4*)(Bh + (size_t)(n0t + r1) * STRIDE + ko);
            pBl0 = *(const uint4*)(Bl + (size_t)(n0t + r0) * STRIDE + ko);
            pBl1 = *(const uint4*)(Bl + (size_t)(n0t + r1) * STRIDE + ko);
        }
#pragma unroll
        for (int kk = 0; kk < 32; kk += 16) {
            uint32_t ah[2][4], al[2][4], bh[8][2], bl[8][2];
#pragma unroll
            for (int mb = 0; mb < 2; mb++) {
                int r = wy * 32 + mb * 16 + gr;
                ah[mb][0] = *(const uint32_t*)&sAh[r][kk + lc2];
                ah[mb][1] = *(const uint32_t*)&sAh[r + 8][kk + lc2];
                ah[mb][2] = *(const uint32_t*)&sAh[r][kk + lc2 + 8];
                ah[mb][3] = *(const uint32_t*)&sAh[r + 8][kk + lc2 + 8];
                al[mb][0] = *(const uint32_t*)&sAl[r][kk + lc2];
                al[mb][1] = *(const uint32_t*)&sAl[r + 8][kk + lc2];
                al[mb][2] = *(const uint32_t*)&sAl[r][kk + lc2 + 8];
                al[mb][3] = *(const uint32_t*)&sAl[r + 8][kk + lc2 + 8];
            }
#pragma unroll
            for (int nb = 0; nb < 8; nb++) {
                int bn = wx * 64 + nb * 8 + gr;
                bh[nb][0] = *(const uint32_t*)&sBh[bn][kk + lc2];
                bh[nb][1] = *(const uint32_t*)&sBh[bn][kk + lc2 + 8];
                bl[nb][0] = *(const uint32_t*)&sBl[bn][kk + lc2];
                bl[nb][1] = *(const uint32_t*)&sBl[bn][kk + lc2 + 8];
            }
#pragma unroll
            for (int mb = 0; mb < 2; mb++)
#pragma unroll
                for (int nb = 0; nb < 8; nb++) {
                    MMA16(acc[mb][nb], ah[mb], bh[nb]);
                    MMA16(acc[mb][nb], ah[mb], bl[nb]);
                    MMA16(acc[mb][nb], al[mb], bh[nb]);
                }
        }
        __syncthreads();
    }
}

#define EPILOGUE_LOOP(BODY)                                                      \
    do {                                                                         \
        int lane = threadIdx.x & 31, wid = threadIdx.x >> 5;                     \
        int wy = wid >> 1, wx = wid & 1;                                         \
        int gr = lane >> 2, lc2 = (lane & 3) * 2;                                \
        _Pragma("unroll")                                                        \
        for (int mb = 0; mb < 2; mb++)                                           \
            _Pragma("unroll")                                                    \
            for (int nb = 0; nb < 8; nb++)                                       \
                _Pragma("unroll")                                                \
                for (int q = 0; q < 4; q++) {                                    \
                    int rr = i0 + wy * 32 + mb * 16 + gr + (q >> 1) * 8;         \
                    int cc = n0t + wx * 64 + nb * 8 + lc2 + (q & 1);             \
                    float a = acc[mb][nb][q];                                    \
                    BODY                                                         \
                }                                                                \
    } while (0)

// ---------------- g_A = L @ G ----------------
__global__ void __launch_bounds__(256) k_lg_mma() {
    __shared__ __align__(16) __nv_bfloat16 sAh[128][40];
    __shared__ __align__(16) __nv_bfloat16 sAl[128][40];
    __shared__ __align__(16) __nv_bfloat16 sBh[128][40];
    __shared__ __align__(16) __nv_bfloat16 sBl[128][40];
    int i0 = blockIdx.x * 128, n0t = blockIdx.y * 128;
    float acc[2][8][4] = {};
    mma128<KDIM>(g_Lhi, g_Llo, g_Gthi, g_Gtlo, i0, n0t, 0, KDIM, acc,
                 sAh, sAl, sBh, sBl);
    EPILOGUE_LOOP({ g_A[(size_t)rr * N0 + cc] = a; });
}

// ---------------- Gram: partial C = At·Bt^T over k-chunk; sel 0=MT 1=XT ----------------
__global__ void __launch_bounds__(256) k_gram_mma(int selA, int selB) {
    __shared__ __align__(16) __nv_bfloat16 sAh[128][40];
    __shared__ __align__(16) __nv_bfloat16 sAl[128][40];
    __shared__ __align__(16) __nv_bfloat16 sBh[128][40];
    __shared__ __align__(16) __nv_bfloat16 sBl[128][40];
    int i0 = blockIdx.x * 128, n0t = blockIdx.y * 128;
    int kbeg = blockIdx.z * (KDIM / 4);
    float acc[2][8][4] = {};
    mma128<KDIM>(selA ? g_XThi : g_MThi, selA ? g_XTlo : g_MTlo,
                 selB ? g_XThi : g_MThi, selB ? g_XTlo : g_MTlo,
                 i0, n0t, kbeg, kbeg + KDIM / 4, acc, sAh, sAl, sBh, sBl);
    float* C = g_part + blockIdx.z * (N0 * N0);
    EPILOGUE_LOOP({ C[(size_t)rr * N0 + cc] = a; });
}

// -- proj; modes:
//  0: G = G - M·Bop            (A-op MR)
//  1: A = M + A - M·Bop, emit XR<-A
//  3: A = A·Bop (Q1), emit Gt<-Q1 rows   (A-op XR)
//  4: A = A - Q1·Bop (Q2), emit MR<-Q2   (A-op Gt)
//  5: G = A - Q2·Bop (Q3 final)          (A-op MR)
__global__ void __launch_bounds__(256) k_proj_mma(int mode) {
    __shared__ __align__(16) __nv_bfloat16 sAh[128][40];
    __shared__ __align__(16) __nv_bfloat16 sAl[128][40];
    __shared__ __align__(16) __nv_bfloat16 sBh[128][40];
    __shared__ __align__(16) __nv_bfloat16 sBl[128][40];
    int i0 = blockIdx.x * 128, n0t = blockIdx.y * 128;
    float acc[2][8][4] = {};
    const __nv_bfloat16 *Ah, *Al;
    if (mode == 3)      { Ah = g_XRhi; Al = g_XRlo; }
    else if (mode == 4) { Ah = g_Gthi; Al = g_Gtlo; }
    else                { Ah = g_MRhi; Al = g_MRlo; }
    mma128<N0>(Ah, Al, g_Bophi, g_Boplo, i0, n0t, 0, N0, acc, sAh, sAl, sBh, sBl);
    int lane = threadIdx.x & 31, wid = threadIdx.x >> 5;
    int wy = wid >> 1, wx = wid & 1;
    int gr = lane >> 2, lc2 = (lane & 3) * 2;
#pragma unroll
    for (int mb = 0; mb < 2; mb++)
#pragma unroll
        for (int nb = 0; nb < 8; nb++)
#pragma unroll
            for (int hf = 0; hf < 2; hf++) {
                int rr = i0 + wy * 32 + mb * 16 + gr + hf * 8;
                int cc = n0t + wx * 64 + nb * 8 + lc2;
                size_t idx = (size_t)rr * N0 + cc;
                float a0 = acc[mb][nb][hf * 2], a1 = acc[mb][nb][hf * 2 + 1];
                if (mode == 0) {
                    g_G[idx]     -= a0;
                    g_G[idx + 1] -= a1;
                } else if (mode == 1) {
                    float v0 = g_M[idx] + g_A[idx] - a0;
                    float v1 = g_M[idx + 1] + g_A[idx + 1] - a1;
                    g_A[idx] = v0; g_A[idx + 1] = v1;
                    __nv_bfloat16 h0 = __float2bfloat16(v0), h1 = __float2bfloat16(v1);
                    ((__nv_bfloat162*)g_XRhi)[idx >> 1] = __nv_bfloat162(h0, h1);
                    ((__nv_bfloat162*)g_XRlo)[idx >> 1] = __nv_bfloat162(
                        __float2bfloat16(v0 - __bfloat162float(h0)),
                        __float2bfloat16(v1 - __bfloat162float(h1)));
                } else if (mode == 3) {
                    g_A[idx] = a0; g_A[idx + 1] = a1;
                    __nv_bfloat16 h0 = __float2bfloat16(a0), h1 = __float2bfloat16(a1);
                    ((__nv_bfloat162*)g_Gthi)[idx >> 1] = __nv_bfloat162(h0, h1);
                    ((__nv_bfloat162*)g_Gtlo)[idx >> 1] = __nv_bfloat162(
                        __float2bfloat16(a0 - __bfloat162float(h0)),
                        __float2bfloat16(a1 - __bfloat162float(h1)));
                } else if (mode == 4) {
                    float v0 = g_A[idx] - a0;
                    float v1 = g_A[idx + 1] - a1;
                    g_A[idx] = v0; g_A[idx + 1] = v1;
                    __nv_bfloat16 h0 = __float2bfloat16(v0), h1 = __float2bfloat16(v1);
                    ((__nv_bfloat162*)g_MRhi)[idx >> 1] = __nv_bfloat162(h0, h1);
                    ((__nv_bfloat162*)g_MRlo)[idx >> 1] = __nv_bfloat162(
                        __float2bfloat16(v0 - __bfloat162float(h0)),
                        __float2bfloat16(v1 - __bfloat162float(h1)));
                } else {
                    g_G[idx]     = g_A[idx] - a0;
                    g_G[idx + 1] = g_A[idx + 1] - a1;
                }
            }
}

// ---------------- x[i] = clip(log(|rowsumsq(G)|)/10, -1, 1) ----------------
__global__ void k_rowsq() {
    int gt = blockIdx.x * 256 + threadIdx.x;
    int row = gt >> 5, lane = gt & 31;
    const float4* rp = (const float4*)&g_G[row * N0];
    float s = 0.f;
#pragma unroll 4
    for (int c = lane; c < 128; c += 32) {
        float4 v = rp[c];
        s += v.x * v.x + v.y * v.y + v.z * v.z + v.w * v.w;
    }
#pragma unroll
    for (int o = 16; o; o >>= 1) s += __shfl_xor_sync(0xffffffffu, s, o);
    if (lane == 0) {
        float x = logf(fabsf(s)) * 0.1f;
        g_x[row] = fminf(1.0f, fmaxf(-1.0f, x));
    }
}

// ---------------- 2-layer LSTM ----------------
__global__ void k_lstm(const float* __restrict__ Lh0, const float* __restrict__ Lc0,
                       const float* __restrict__ Wih0, const float* __restrict__ Whh0,
                       const float* __restrict__ bih0, const float* __restrict__ bhh0,
                       const float* __restrict__ Wih1, const float* __restrict__ Whh1,
                       const float* __restrict__ bih1, const float* __restrict__ bhh1,
                       const float* __restrict__ Wl, const float* __restrict__ bl,
                       float* __restrict__ out) {
    __shared__ float sWih0[80], sWhh0[1600], sb0[80];
    __shared__ float sWih1[1600], sWhh1[1600], sb1[80];
    __shared__ float sWl[20], sbl[1];
    int t = threadIdx.x;
    for (int i = t; i < 80; i += 256) {
        sWih0[i] = Wih0[i];
        sb0[i] = bih0[i] + bhh0[i];
        sb1[i] = bih1[i] + bhh1[i];
    }
    for (int i = t; i < 1600; i += 256) {
        sWhh0[i] = Whh0[i];
        sWih1[i] = Wih1[i];
        sWhh1[i] = Whh1[i];
    }
    if (t < 20) sWl[t] = Wl[t];
    if (t == 0) sbl[0] = bl[0];
    __syncthreads();

    int i = blockIdx.x * 256 + t;
    float x = g_x[i];
    float h0p[20], h1p[20], h0n[20];
#pragma unroll
    for (int h = 0; h < 20; h++) {
        h0p[h] = Lh0[i * 20 + h];
        h1p[h] = Lh0[92160 + i * 20 + h];
    }
#pragma unroll
    for (int h = 0; h < 20; h++) {
        float pi = sb0[h]      + x * sWih0[h];
        float pf = sb0[20 + h] + x * sWih0[20 + h];
        float pg = sb0[40 + h] + x * sWih0[40 + h];
        float po = sb0[60 + h] + x * sWih0[60 + h];
#pragma unroll
        for (int m = 0; m < 20; m++) {
            float hm = h0p[m];
            pi += hm * sWhh0[h * 20 + m];
            pf += hm * sWhh0[(20 + h) * 20 + m];
            pg += hm * sWhh0[(40 + h) * 20 + m];
            po += hm * sWhh0[(60 + h) * 20 + m];
        }
        float c0 = Lc0[i * 20 + h];
        float c = sigf(pf) * c0 + sigf(pi) * tanhf(pg);
        float hh = sigf(po) * tanhf(c);
        h0n[h] = hh;
        out[O_H + i * 20 + h] = hh;
        out[O_C + i * 20 + h] = c;
    }
    float lacc = sbl[0];
#pragma unroll
    for (int h = 0; h < 20; h++) {
        float pi = sb1[h], pf = sb1[20 + h], pg = sb1[40 + h], po = sb1[60 + h];
#pragma unroll
        for (int m = 0; m < 20; m++) {
            float a = h0n[m], b = h1p[m];
            pi += a * sWih1[h * 20 + m]        + b * sWhh1[h * 20 + m];
            pf += a * sWih1[(20 + h) * 20 + m] + b * sWhh1[(20 + h) * 20 + m];
            pg += a * sWih1[(40 + h) * 20 + m] + b * sWhh1[(40 + h) * 20 + m];
            po += a * sWih1[(60 + h) * 20 + m] + b * sWhh1[(60 + h) * 20 + m];
        }
        float c1 = Lc0[92160 + i * 20 + h];
        float c = sigf(pf) * c1 + sigf(pi) * tanhf(pg);
        float hh = sigf(po) * tanhf(c);
        out[O_H + 92160 + i * 20 + h] = hh;
        out[O_C + 92160 + i * 20 + h] = c;
        lacc += hh * sWl[h];
    }
    g_lraw[i] = lacc * 0.1f;
}

__global__ void k_mean() {
    __shared__ float sm[256];
    int t = threadIdx.x;
    float s = 0.f;
    for (int i = t; i < KDIM; i += 256) s += g_lraw[i];
    sm[t] = s;
    __syncthreads();
    for (int o = 128; o; o >>= 1) {
        if (t < o) sm[t] += sm[t + o];
        __syncthreads();
    }
    if (t == 0) g_mean = sm[0] * (1.0f / KDIM);
}

// ---------------- L (fp32 out + split-bf16) ----------------
__global__ void k_build_L(const float4* __restrict__ Lb, float4* __restrict__ outL) {
    int gid = blockIdx.x * 256 + threadIdx.x;
    int base = gid * 4;
    int i = base / KDIM;
    int j0 = base - i * KDIM;
    float dv = g_lraw[i] - g_mean + 1.0f;
    float4 lb = Lb[gid];
    float4 r;
    r.x = fmaxf((j0 + 0 == i) ? dv : 0.0f, lb.x);
    r.y = fmaxf((j0 + 1 == i) ? dv : 0.0f, lb.y);
    r.z = fmaxf((j0 + 2 == i) ? dv : 0.0f, lb.z);
    r.w = fmaxf((j0 + 3 == i) ? dv : 0.0f, lb.w);
    outL[gid] = r;
    __nv_bfloat16 hx = __float2bfloat16(r.x), hy = __float2bfloat16(r.y);
    __nv_bfloat16 hz = __float2bfloat16(r.z), hw = __float2bfloat16(r.w);
    __nv_bfloat162* ph = (__nv_bfloat162*)g_Lhi;
    __nv_bfloat162* pl = (__nv_bfloat162*)g_Llo;
    ph[2 * gid]     = __nv_bfloat162(hx, hy);
    ph[2 * gid + 1] = __nv_bfloat162(hz, hw);
    pl[2 * gid]     = __nv_bfloat162(__float2bfloat16(r.x - __bfloat162float(hx)),
                                     __float2bfloat16(r.y - __bfloat162float(hy)));
    pl[2 * gid + 1] = __nv_bfloat162(__float2bfloat16(r.z - __bfloat162float(hz)),
                                     __float2bfloat16(r.w - __bfloat162float(hw)));
}

// -------- left-looking chol, merged factor+TRSM (2 syncs/column) --------
__global__ void k_chol_left(int p) {
    __shared__ float S1[64][65];   // D
    __shared__ float S2[64][65];   // C
    int bi = p + blockIdx.x;
    bool offd = (bi != p);
    int t = threadIdx.x, ty = t >> 4, tx = t & 15;
    float accC[4][4] = {}, accD[4][4];
#pragma unroll
    for (int u = 0; u < 4; u++)
#pragma unroll
        for (int v = 0; v < 4; v++) {
            accD[u][v] = g_S[(p * 64 + ty * 4 + u) * N0 + p * 64 + tx * 4 + v];
            if (offd)
                accC[u][v] = g_S[(bi * 64 + ty * 4 + u) * N0 + p * 64 + tx * 4 + v];
        }
    for (int kb = 0; kb < p; kb++) {
        for (int idx = t; idx < 4096; idx += 256) {
            int r = idx >> 6, c = idx & 63;
            S1[r][c] = g_S[(bi * 64 + r) * N0 + kb * 64 + c];
            S2[r][c] = g_S[(p * 64 + r) * N0 + kb * 64 + c];
        }
        __syncthreads();
#pragma unroll 8
        for (int k = 0; k < 64; k++) {
            float lb_[4], lp_[4], lpr[4];
#pragma unroll
            for (int u = 0; u < 4; u++) {
                lb_[u] = S1[ty * 4 + u][k];
                lp_[u] = S2[tx * 4 + u][k];
                lpr[u] = S2[ty * 4 + u][k];
            }
#pragma unroll
            for (int u = 0; u < 4; u++)
#pragma unroll
                for (int v = 0; v < 4; v++) {
                    accC[u][v] -= lb_[u] * lp_[v];
                    accD[u][v] -= lpr[u] * lp_[v];
                }
        }
        __syncthreads();
    }
#pragma unroll
    for (int u = 0; u < 4; u++)
#pragma unroll
        for (int v = 0; v < 4; v++) {
            S1[ty * 4 + u][tx * 4 + v] = accD[u][v];
            S2[ty * 4 + u][tx * 4 + v] = accC[u][v];
        }
    __syncthreads();
    float mydj = 0.0f;
    for (int j = 0; j < 64; j++) {
        float dj = sqrtf(fmaxf(S1[j][j], 1e-30f));  // clamped pivot; redundant compute
        if (t == j) mydj = dj;
        float inv = 1.0f / dj;
        for (int r = j + 1 + t; r < 64; r += 256) S1[r][j] *= inv;
        if (offd && t < 64) S2[t][j] *= inv;
        __syncthreads();
        for (int idx = t; idx < 4096; idx += 256) {
            int r = idx >> 6, c = idx & 63;
            if (c > j) {
                float dcj = S1[c][j];
                if (r >= c) S1[r][c] -= S1[r][j] * dcj;
                if (offd)   S2[r][c] -= S2[r][j] * dcj;
            }
        }
        __syncthreads();
    }
    if (t < 64) S1[t][t] = mydj;
    __syncthreads();
    if (!offd) {
        for (int idx = t; idx < 4096; idx += 256) {
            int r = idx >> 6, c = idx & 63;
            g_S[(p * 64 + r) * N0 + p * 64 + c] = S1[r][c];
        }
    } else {
        for (int idx = t; idx < 4096; idx += 256) {
            int r = idx >> 6, c = idx & 63;
            g_S[(bi * 64 + r) * N0 + p * 64 + c] = S2[r][c];
        }
    }
}

// -------- recursive-doubling triangular inverse: Linv -> g_part --------
__global__ void k_inv_diag() {
    __shared__ float S1[64][65];
    __shared__ float S2[64][65];
    int i = blockIdx.x;
    int t = threadIdx.x;
    for (int idx = t; idx < 4096; idx += 256) {
        int r = idx >> 6, c = idx & 63;
        S1[r][c] = g_S[(i * 64 + r) * N0 + i * 64 + c];
    }
    __syncthreads();
    if (t < 64) {
        int c = t;
        for (int r = 0; r < 64; r++) {
            if (r < c) { S2[r][c] = 0.0f; continue; }
            float s = (r == c) ? 1.0f : 0.0f;
            for (int k = c; k < r; k++) s -= S1[r][k] * S2[k][c];
            S2[r][c] = s / S1[r][r];
        }
    }
    __syncthreads();
    for (int idx = t; idx < 4096; idx += 256) {
        int r = idx >> 6, c = idx & 63;
        g_part[(i * 64 + r) * N0 + i * 64 + c] = S2[r][c];
    }
}

// P[r][c] = sum_{m} L[r][m] * Linv[m][c]  (block units) -> g_Sym
__global__ void k_tri_P(int h) {
    __shared__ float SA[64][65];
    __shared__ float SB[64][65];
    int hh = h * h;
    int q = blockIdx.x / hh, loc = blockIdx.x % hh;
    int ri = loc / h, ci = loc % h;
    int r = 2 * q * h + h + ri, c = 2 * q * h + ci;
    int t = threadIdx.x, ty = t >> 4, tx = t & 15;
    float acc[4][4] = {};
    for (int m = c; m < 2 * q * h + h; m++) {
        for (int idx = t; idx < 4096; idx += 256) {
            int rr = idx >> 6, cc = idx & 63;
            SA[rr][cc] = g_S[(r * 64 + rr) * N0 + m * 64 + cc];
            SB[rr][cc] = g_part[(m * 64 + rr) * N0 + c * 64 + cc];
        }
        __syncthreads();
#pragma unroll 8
        for (int k = 0; k < 64; k++)
#pragma unroll
            for (int u = 0; u < 4; u++)
#pragma unroll
                for (int v = 0; v < 4; v++)
                    acc[u][v] += SA[ty * 4 + u][k] * SB[k][tx * 4 + v];
        __syncthreads();
    }
#pragma unroll
    for (int u = 0; u < 4; u++)
#pragma unroll
        for (int v = 0; v < 4; v++)
            g_Sym[(r * 64 + ty * 4 + u) * N0 + c * 64 + tx * 4 + v] = acc[u][v];
}

// X[r][c] = -sum_{m} Linv[r][m] * P[m][c] -> g_part
__global__ void k_tri_X(int h) {
    __shared__ float SA[64][65];
    __shared__ float SB[64][65];
    int hh = h * h;
    int q = blockIdx.x / hh, loc = blockIdx.x % hh;
    int ri = loc / h, ci = loc % h;
    int r = 2 * q * h + h + ri, c = 2 * q * h + ci;
    int t = threadIdx.x, ty = t >> 4, tx = t & 15;
    float acc[4][4] = {};
    for (int m = 2 * q * h + h; m <= r; m++) {
        for (int idx = t; idx < 4096; idx += 256) {
            int rr = idx >> 6, cc = idx & 63;
            SA[rr][cc] = g_part[(r * 64 + rr) * N0 + m * 64 + cc];
            SB[rr][cc] = g_Sym[(m * 64 + rr) * N0 + c * 64 + cc];
        }
        __syncthreads();
#pragma unroll 8
        for (int k = 0; k < 64; k++)
#pragma unroll
            for (int u = 0; u < 4; u++)
#pragma unroll
                for (int v = 0; v < 4; v++)
                    acc[u][v] += SA[ty * 4 + u][k] * SB[k][tx * 4 + v];
        __syncthreads();
    }
#pragma unroll
    for (int u = 0; u < 4; u++)
#pragma unroll
        for (int v = 0; v < 4; v++)
            g_part[(r * 64 + ty * 4 + u) * N0 + c * 64 + tx * 4 + v] = -acc[u][v];
}

// ---------------- new_s = Q^T ----------------
__global__ void k_write_s(float* __restrict__ outS) {
    __shared__ float tile[32][33];
    int kB = blockIdx.x * 32, nB = blockIdx.y * 32;
    int tx = threadIdx.x, ty = threadIdx.y;
#pragma unroll
    for (int r = 0; r < 32; r += 8)
        tile[ty + r][tx] = g_G[(kB + ty + r) * N0 + nB + tx];
    __syncthreads();
#pragma unroll
    for (int r = 0; r < 32; r += 8)
        outS[(nB + ty + r) * KDIM + kB + tx] = tile[tx][ty + r];
}

extern "C" void kernel_launch(void* const* d_in, const int* in_sizes, int n_in,
                              void* d_out, int out_size) {
    const float* e    = (const float*)d_in[0];
    const float* eg   = (const float*)d_in[1];
    const float* s    = (const float*)d_in[2];
    const float* sg   = (const float*)d_in[3];
    const float* Lh0  = (const float*)d_in[4];
    const float* Lc0  = (const float*)d_in[5];
    const float* Lb   = (const float*)d_in[6];
    const float* Wih0 = (const float*)d_in[7];
    const float* Whh0 = (const float*)d_in[8];
    const float* bih0 = (const float*)d_in[9];
    const float* bhh0 = (const float*)d_in[10];
    const float* Wih1 = (const float*)d_in[11];
    const float* Whh1 = (const float*)d_in[12];
    const float* bih1 = (const float*)d_in[13];
    const float* bhh1 = (const float*)d_in[14];
    const float* Wl   = (const float*)d_in[15];
    const float* bl   = (const float*)d_in[16];
    const float* e_lr = (const float*)d_in[17];
    const float* s_lr = (const float*)d_in[18];
    float* out = (float*)d_out;

    k_update_e<<<16384, 256>>>((const float4*)e, (const float4*)eg, e_lr,
                               (float4*)(out + O_E));
    k_make_MMg<<<dim3(144, 16), dim3(32, 8)>>>(s, sg, s_lr);
    k_stsplit<<<2304, 256>>>((const float4*)s, s_lr, 0);   // M^T  -> MT
    k_stsplit<<<2304, 256>>>((const float4*)sg, s_lr, 1);  // Mg^T -> XT
    k_rsplit<<<2304, 256>>>();                             // M rows -> MR
    // Sym = sym(M^T Mg) (+Bop); G = Mg - M @ Sym
    k_gram_mma<<<dim3(4, 4, 4), 256>>>(0, 1);
    k_reduce_sym<<<512, 512>>>(0, 0);
    k_proj_mma<<<dim3(36, 4), 256>>>(0);
    // LogAndSign -> LSTM -> L
    k_rowsq<<<576, 256>>>();
    k_lstm<<<18, 256>>>(Lh0, Lc0, Wih0, Whh0, bih0, bhh0,
                        Wih1, Whh1, bih1, bhh1, Wl, bl, out);
    k_mean<<<1, 256>>>();
    k_build_L<<<20736, 256>>>((const float4*)Lb, (float4*)(out + O_L));
    // LG on tensor cores
    k_tsplit<<<dim3(144, 16), dim3(32, 8)>>>(3);           // G^T -> Gt
    k_lg_mma<<<dim3(36, 4), 256>>>();
    // A = M + LG - M @ sym(M^T LG)   (mode-1 also emits A row-splits -> XR)
    k_tsplit<<<dim3(144, 16), dim3(32, 8)>>>(1);           // LG^T -> XT
    k_gram_mma<<<dim3(4, 4, 4), 256>>>(0, 1);
    k_reduce_sym<<<512, 512>>>(0, 0);
    k_proj_mma<<<dim3(36, 4), 256>>>(1);
    // CholQR pass 1: fp32 Gram (precision-critical) -> chol (8) -> Linv -> Q1
    k_gemm_tn<<<dim3(8, 8, 4), 256>>>();
    k_reduce_sym<<<512, 512>>>(1, -1);
    for (int p = 0; p < 8; p++) k_chol_left<<<8 - p, 256>>>(p);
    k_inv_diag<<<8, 256>>>();
    for (int h = 1; h <= 4; h <<= 1) {
        int nb = (4 / h) * h * h;
        k_tri_P<<<nb, 256>>>(h);
        k_tri_X<<<nb, 256>>>(h);
    }
    k_bsplit_linv<<<512, 512>>>();
    k_proj_mma<<<dim3(36, 4), 256>>>(3);                   // Q1 (+rows -> Gt)
    // Newton pass A: Q2 = Q1 - Q1·U1
    k_tsplit<<<dim3(144, 16), dim3(32, 8)>>>(1);           // Q1^T -> XT
    k_gram_mma<<<dim3(4, 4, 4), 256>>>(1, 1);
    k_reduce_sym<<<512, 512>>>(0, 1);
    k_proj_mma<<<dim3(36, 4), 256>>>(4);                   // Q2 (+rows -> MR)
    // Newton pass B: Q3 = Q2 - Q2·U2
    k_tsplit<<<dim3(144, 16), dim3(32, 8)>>>(1);           // Q2^T -> XT
    k_gram_mma<<<dim3(4, 4, 4), 256>>>(1, 1);
    k_reduce_sym<<<512, 512>>>(0, 1);
    k_proj_mma<<<dim3(36, 4), 256>>>(5);                   // G = Q3
    // new_s
    k_write_s<<<dim3(144, 16), dim3(32, 8)>>>(out + O_S);
}

// round 17
// speedup vs baseline: 1.0618x; 1.0618x over previous
#include <cuda_runtime.h>
#include <cuda_bf16.h>
#include <math.h>
#include <stdint.h>

#define KDIM 4608
#define N0   512
#define WDC  0.0005f

// output layout (floats): new_e, new_s, L, hn, cn
#define O_E 0
#define O_S 16777216
#define O_L 19136512
#define O_H 40370176
#define O_C 40554496

// ---------------- scratch ----------------
__device__ __align__(256) float g_M[KDIM * N0];
__device__ __align__(256) float g_G[KDIM * N0];      // Mg -> G -> Q2 (final)
__device__ __align__(256) float g_A[KDIM * N0];      // LG -> A -> Q1
__device__ __align__(256) float g_S[N0 * N0];        // Gram -> chol L (lower)
__device__ __align__(256) float g_Sym[N0 * N0];      // Sym / P-scratch for trinv
__device__ __align__(256) float g_part[4 * N0 * N0]; // split-K partials / Linv
__device__ __align__(256) float g_x[KDIM];
__device__ __align__(256) float g_lraw[KDIM];
__device__ float g_mean;
__device__ __align__(256) __nv_bfloat16 g_Lhi[(size_t)KDIM * KDIM];
__device__ __align__(256) __nv_bfloat16 g_Llo[(size_t)KDIM * KDIM];
__device__ __align__(256) __nv_bfloat16 g_Gthi[(size_t)N0 * KDIM];  // G^T; later Q1 rows
__device__ __align__(256) __nv_bfloat16 g_Gtlo[(size_t)N0 * KDIM];
__device__ __align__(256) __nv_bfloat16 g_MThi[(size_t)N0 * KDIM];
__device__ __align__(256) __nv_bfloat16 g_MTlo[(size_t)N0 * KDIM];
__device__ __align__(256) __nv_bfloat16 g_XThi[(size_t)N0 * KDIM];
__device__ __align__(256) __nv_bfloat16 g_XTlo[(size_t)N0 * KDIM];
__device__ __align__(256) __nv_bfloat16 g_MRhi[(size_t)KDIM * N0];  // M rows
__device__ __align__(256) __nv_bfloat16 g_MRlo[(size_t)KDIM * N0];
__device__ __align__(256) __nv_bfloat16 g_XRhi[(size_t)KDIM * N0];  // A rows
__device__ __align__(256) __nv_bfloat16 g_XRlo[(size_t)KDIM * N0];
__device__ __align__(256) __nv_bfloat16 g_Bophi[N0 * N0];
__device__ __align__(256) __nv_bfloat16 g_Boplo[N0 * N0];

__device__ __forceinline__ float sigf(float z) { return 1.0f / (1.0f + expf(-z)); }

#define MMA16(ACC, AV, BV)                                                       \
    asm volatile("mma.sync.aligned.m16n8k16.row.col.f32.bf16.bf16.f32 "          \
                 "{%0,%1,%2,%3}, {%4,%5,%6,%7}, {%8,%9}, {%0,%1,%2,%3};"         \
                 : "+f"((ACC)[0]), "+f"((ACC)[1]), "+f"((ACC)[2]), "+f"((ACC)[3])\
                 : "r"((AV)[0]), "r"((AV)[1]), "r"((AV)[2]), "r"((AV)[3]),       \
                   "r"((BV)[0]), "r"((BV)[1]))

// ---------------- new_e ----------------
__global__ void k_update_e(const float4* __restrict__ e, const float4* __restrict__ eg,
                           const float* __restrict__ e_lr, float4* __restrict__ out) {
    int i = blockIdx.x * 256 + threadIdx.x;
    float lr = *e_lr;
    float4 a = e[i], g = eg[i];
    float4 r;
    r.x = a.x - lr * (g.x + WDC * a.x);
    r.y = a.y - lr * (g.y + WDC * a.y);
    r.z = a.z - lr * (g.z + WDC * a.z);
    r.w = a.w - lr * (g.w + WDC * a.w);
    out[i] = r;
}

// ---------------- M, Mg ----------------
__global__ void k_make_MMg(const float* __restrict__ s, const float* __restrict__ sg,
                           const float* __restrict__ s_lr) {
    __shared__ float t0[32][33];
    __shared__ float t1[32][33];
    int iB = blockIdx.x * 32, jB = blockIdx.y * 32;
    int tx = threadIdx.x, ty = threadIdx.y;
#pragma unroll
    for (int r = 0; r < 32; r += 8) {
        t0[ty + r][tx] = s [(jB + ty + r) * KDIM + iB + tx];
        t1[ty + r][tx] = sg[(jB + ty + r) * KDIM + iB + tx];
    }
    __syncthreads();
    float nslr = -(*s_lr);
#pragma unroll
    for (int r = 0; r < 32; r += 8) {
        int i = iB + ty + r;
        g_M[i * N0 + jB + tx] = t0[tx][ty + r];
        g_G[i * N0 + jB + tx] = nslr * t1[tx][ty + r];
    }
}

// ---------------- split directly from s/sg (already M^T layout) ----------------
__global__ void k_stsplit(const float4* __restrict__ src, const float* __restrict__ lr,
                          int sel) {
    int gid = blockIdx.x * 256 + threadIdx.x;
    float sc = sel ? -(*lr) : 1.0f;
    float4 v = src[gid];
    v.x *= sc; v.y *= sc; v.z *= sc; v.w *= sc;
    __nv_bfloat162* dh = (__nv_bfloat162*)(sel ? g_XThi : g_MThi);
    __nv_bfloat162* dl = (__nv_bfloat162*)(sel ? g_XTlo : g_MTlo);
    __nv_bfloat16 hx = __float2bfloat16(v.x), hy = __float2bfloat16(v.y);
    __nv_bfloat16 hz = __float2bfloat16(v.z), hw = __float2bfloat16(v.w);
    dh[2 * gid]     = __nv_bfloat162(hx, hy);
    dh[2 * gid + 1] = __nv_bfloat162(hz, hw);
    dl[2 * gid]     = __nv_bfloat162(__float2bfloat16(v.x - __bfloat162float(hx)),
                                     __float2bfloat16(v.y - __bfloat162float(hy)));
    dl[2 * gid + 1] = __nv_bfloat162(__float2bfloat16(v.z - __bfloat162float(hz)),
                                     __float2bfloat16(v.w - __bfloat162float(hw)));
}

// ---------------- fp32 Gram (pass-1 only): C = A^T A split-K ----------------
__global__ void k_gemm_tn() {
    const float* A = g_A;
    __shared__ __align__(16) float As[16][68];
    __shared__ __align__(16) float Bs[16][68];
    int a0 = blockIdx.x * 64, b0 = blockIdx.y * 64;
    int k0 = blockIdx.z * (KDIM / 4);
    int t = threadIdx.x, tx = t & 15, ty = t >> 4;
    int lr = t >> 4, lc = t & 15;
    float acc[4][4] = {};
    for (int kk = 0; kk < KDIM / 4; kk += 16) {
        float4 va = *(const float4*)&A[(k0 + kk + lr) * N0 + a0 + lc * 4];
        float4 vb = *(const float4*)&A[(k0 + kk + lr) * N0 + b0 + lc * 4];
        *(float4*)&As[lr][lc * 4] = va;
        *(float4*)&Bs[lr][lc * 4] = vb;
        __syncthreads();
#pragma unroll
        for (int k = 0; k < 16; k++) {
            float4 av = *(const float4*)&As[k][ty * 4];
            float4 bv = *(const float4*)&Bs[k][tx * 4];
            float a_[4] = {av.x, av.y, av.z, av.w};
            float b_[4] = {bv.x, bv.y, bv.z, bv.w};
#pragma unroll
            for (int u = 0; u < 4; u++)
#pragma unroll
                for (int v = 0; v < 4; v++) acc[u][v] += a_[u] * b_[v];
        }
        __syncthreads();
    }
    float* C = g_part + blockIdx.z * (N0 * N0);
#pragma unroll
    for (int u = 0; u < 4; u++)
#pragma unroll
        for (int v = 0; v < 4; v++)
            C[(a0 + ty * 4 + u) * N0 + (b0 + tx * 4 + v)] = acc[u][v];
}

// ------- reduce split-K + symmetrize; optionally emit Bop split (bmode -1/0/1) -------
__global__ void k_reduce_sym(int dst, int bmode) {
    int idx = blockIdx.x * 512 + threadIdx.x;
    int a = idx >> 9, b = idx & 511;
    float s1 = 0.f, s2 = 0.f;
#pragma unroll
    for (int z = 0; z < 4; z++) {
        s1 += g_part[z * N0 * N0 + idx];
        s2 += g_part[z * N0 * N0 + b * N0 + a];
    }
    float v = 0.5f * (s1 + s2);
    if (dst == 0) g_Sym[idx] = v; else g_S[idx] = v;
    if (bmode >= 0) {
        float bv = v;
        if (bmode == 1)
            bv = (b < a) ? v : ((b == a) ? 0.5f * (v - 1.0f) : 0.0f);
        __nv_bfloat16 h = __float2bfloat16(bv);
        g_Bophi[idx] = h;
        g_Boplo[idx] = __float2bfloat16(bv - __bfloat162float(h));
    }
}

// ---------------- transpose + split: sel 1:A->XT 3:G->Gt ----------------
__global__ void k_tsplit(int sel) {
    __shared__ float tile[32][33];
    const float* src = (sel == 1) ? g_A : g_G;
    __nv_bfloat16* dh = (sel == 3) ? g_Gthi : g_XThi;
    __nv_bfloat16* dl = (sel == 3) ? g_Gtlo : g_XTlo;
    int kB = blockIdx.x * 32, nB = blockIdx.y * 32;
    int tx = threadIdx.x, ty = threadIdx.y;
#pragma unroll
    for (int r = 0; r < 32; r += 8)
        tile[ty + r][tx] = src[(kB + ty + r) * N0 + nB + tx];
    __syncthreads();
#pragma unroll
    for (int r = 0; r < 32; r += 8) {
        float v = tile[tx][ty + r];
        __nv_bfloat16 h = __float2bfloat16(v);
        size_t idx = (size_t)(nB + ty + r) * KDIM + kB + tx;
        dh[idx] = h;
        dl[idx] = __float2bfloat16(v - __bfloat162float(h));
    }
}

// ---------------- row split: M -> MR ----------------
__global__ void k_rsplit() {
    int gid = blockIdx.x * 256 + threadIdx.x;
    const float4* src = (const float4*)g_M;
    __nv_bfloat162* dh = (__nv_bfloat162*)g_MRhi;
    __nv_bfloat162* dl = (__nv_bfloat162*)g_MRlo;
    float4 v = src[gid];
    __nv_bfloat16 hx = __float2bfloat16(v.x), hy = __float2bfloat16(v.y);
    __nv_bfloat16 hz = __float2bfloat16(v.z), hw = __float2bfloat16(v.w);
    dh[2 * gid]     = __nv_bfloat162(hx, hy);
    dh[2 * gid + 1] = __nv_bfloat162(hz, hw);
    dl[2 * gid]     = __nv_bfloat162(__float2bfloat16(v.x - __bfloat162float(hx)),
                                     __float2bfloat16(v.y - __bfloat162float(hy)));
    dl[2 * gid + 1] = __nv_bfloat162(__float2bfloat16(v.z - __bfloat162float(hz)),
                                     __float2bfloat16(v.w - __bfloat162float(hw)));
}

// ---------------- Bop from Linv (g_part, lower-masked) ----------------
__global__ void k_bsplit_linv() {
    int j = blockIdx.x, a = threadIdx.x;
    float v = (a <= j) ? g_part[j * N0 + a] : 0.0f;
    __nv_bfloat16 h = __float2bfloat16(v);
    g_Bophi[j * N0 + a] = h;
    g_Boplo[j * N0 + a] = __float2bfloat16(v - __bfloat162float(h));
}

// ======== 128x128-tile split-bf16 HMMA core (3-term), warp tile 32x64 ========
template <int STRIDE>
__device__ __forceinline__ void mma128(
    const __nv_bfloat16* __restrict__ Ah, const __nv_bfloat16* __restrict__ Al,
    const __nv_bfloat16* __restrict__ Bh, const __nv_bfloat16* __restrict__ Bl,
    int i0, int n0t, int kbeg, int kend, float acc[2][8][4],
    __nv_bfloat16 (*sAh)[40], __nv_bfloat16 (*sAl)[40],
    __nv_bfloat16 (*sBh)[40], __nv_bfloat16 (*sBl)[40]) {
    int t = threadIdx.x, lane = t & 31, wid = t >> 5;
    int wy = wid >> 1, wx = wid & 1;
    int r0 = t >> 2, c0 = (t & 3) * 8;
    int r1 = r0 + 64;
    int gr = lane >> 2, lc2 = (lane & 3) * 2;
    uint4 pAh0 = *(const uint4*)(Ah + (size_t)(i0 + r0) * STRIDE + kbeg + c0);
    uint4 pAh1 = *(const uint4*)(Ah + (size_t)(i0 + r1) * STRIDE + kbeg + c0);
    uint4 pAl0 = *(const uint4*)(Al + (size_t)(i0 + r0) * STRIDE + kbeg + c0);
    uint4 pAl1 = *(const uint4*)(Al + (size_t)(i0 + r1) * STRIDE + kbeg + c0);
    uint4 pBh0 = *(const uint4*)(Bh + (size_t)(n0t + r0) * STRIDE + kbeg + c0);
    uint4 pBh1 = *(const uint4*)(Bh + (size_t)(n0t + r1) * STRIDE + kbeg + c0);
    uint4 pBl0 = *(const uint4*)(Bl + (size_t)(n0t + r0) * STRIDE + kbeg + c0);
    uint4 pBl1 = *(const uint4*)(Bl + (size_t)(n0t + r1) * STRIDE + kbeg + c0);
    for (int k0 = kbeg; k0 < kend; k0 += 32) {
        *(uint4*)&sAh[r0][c0] = pAh0;
        *(uint4*)&sAh[r1][c0] = pAh1;
        *(uint4*)&sAl[r0][c0] = pAl0;
        *(uint4*)&sAl[r1][c0] = pAl1;
        *(uint4*)&sBh[r0][c0] = pBh0;
        *(uint4*)&sBh[r1][c0] = pBh1;
        *(uint4*)&sBl[r0][c0] = pBl0;
        *(uint4*)&sBl[r1][c0] = pBl1;
        __syncthreads();
        if (k0 + 32 < kend) {
            size_t ko = (size_t)(k0 + 32 + c0);
            pAh0 = *(const uint4*)(Ah + (size_t)(i0 + r0) * STRIDE + ko);
            pAh1 = *(const uint4*)(Ah + (size_t)(i0 + r1) * STRIDE + ko);
            pAl0 = *(const uint4*)(Al + (size_t)(i0 + r0) * STRIDE + ko);
            pAl1 = *(const uint4*)(Al + (size_t)(i0 + r1) * STRIDE + ko);
            pBh0 = *(const uint4*)(Bh + (size_t)(n0t + r0) * STRIDE + ko);
            pBh1 = *(const uint4*)(Bh + (size_t)(n0t + r1) * STRIDE + ko);
            pBl0 = *(const uint4*)(Bl + (size_t)(n0t + r0) * STRIDE + ko);
            pBl1 = *(const uint4*)(Bl + (size_t)(n0t + r1) * STRIDE + ko);
        }
#pragma unroll
        for (int kk = 0; kk < 32; kk += 16) {
            uint32_t ah[2][4], al[2][4], bh[8][2], bl[8][2];
#pragma unroll
            for (int mb = 0; mb < 2; mb++) {
                int r = wy * 32 + mb * 16 + gr;
                ah[mb][0] = *(const uint32_t*)&sAh[r][kk + lc2];
                ah[mb][1] = *(const uint32_t*)&sAh[r + 8][kk + lc2];
                ah[mb][2] = *(const uint32_t*)&sAh[r][kk + lc2 + 8];
                ah[mb][3] = *(const uint32_t*)&sAh[r + 8][kk + lc2 + 8];
                al[mb][0] = *(const uint32_t*)&sAl[r][kk + lc2];
                al[mb][1] = *(const uint32_t*)&sAl[r + 8][kk + lc2];
                al[mb][2] = *(const uint32_t*)&sAl[r][kk + lc2 + 8];
                al[mb][3] = *(const uint32_t*)&sAl[r + 8][kk + lc2 + 8];
            }
#pragma unroll
            for (int nb = 0; nb < 8; nb++) {
                int bn = wx * 64 + nb * 8 + gr;
                bh[nb][0] = *(const uint32_t*)&sBh[bn][kk + lc2];
                bh[nb][1] = *(const uint32_t*)&sBh[bn][kk + lc2 + 8];
                bl[nb][0] = *(const uint32_t*)&sBl[bn][kk + lc2];
                bl[nb][1] = *(const uint32_t*)&sBl[bn][kk + lc2 + 8];
            }
#pragma unroll
            for (int mb = 0; mb < 2; mb++)
#pragma unroll
                for (int nb = 0; nb < 8; nb++) {
                    MMA16(acc[mb][nb], ah[mb], bh[nb]);
                    MMA16(acc[mb][nb], ah[mb], bl[nb]);
                    MMA16(acc[mb][nb], al[mb], bh[nb]);
                }
        }
        __syncthreads();
    }
}

#define EPILOGUE_LOOP(BODY)                                                      \
    do {                                                                         \
        int lane = threadIdx.x & 31, wid = threadIdx.x >> 5;                     \
        int wy = wid >> 1, wx = wid & 1;                                         \
        int gr = lane >> 2, lc2 = (lane & 3) * 2;                                \
        _Pragma("unroll")                                                        \
        for (int mb = 0; mb < 2; mb++)                                           \
            _Pragma("unroll")                                                    \
            for (int nb = 0; nb < 8; nb++)                                       \
                _Pragma("unroll")                                                \
                for (int q = 0; q < 4; q++) {                                    \
                    int rr = i0 + wy * 32 + mb * 16 + gr + (q >> 1) * 8;         \
                    int cc = n0t + wx * 64 + nb * 8 + lc2 + (q & 1);             \
                    float a = acc[mb][nb][q];                                    \
                    BODY                                                         \
                }                                                                \
    } while (0)

// ---------------- g_A = L @ G ----------------
__global__ void __launch_bounds__(256) k_lg_mma() {
    __shared__ __align__(16) __nv_bfloat16 sAh[128][40];
    __shared__ __align__(16) __nv_bfloat16 sAl[128][40];
    __shared__ __align__(16) __nv_bfloat16 sBh[128][40];
    __shared__ __align__(16) __nv_bfloat16 sBl[128][40];
    int i0 = blockIdx.x * 128, n0t = blockIdx.y * 128;
    float acc[2][8][4] = {};
    mma128<KDIM>(g_Lhi, g_Llo, g_Gthi, g_Gtlo, i0, n0t, 0, KDIM, acc,
                 sAh, sAl, sBh, sBl);
    EPILOGUE_LOOP({ g_A[(size_t)rr * N0 + cc] = a; });
}

// ---------------- Gram: partial C = At·Bt^T over k-chunk; sel 0=MT 1=XT ----------------
__global__ void __launch_bounds__(256) k_gram_mma(int selA, int selB) {
    __shared__ __align__(16) __nv_bfloat16 sAh[128][40];
    __shared__ __align__(16) __nv_bfloat16 sAl[128][40];
    __shared__ __align__(16) __nv_bfloat16 sBh[128][40];
    __shared__ __align__(16) __nv_bfloat16 sBl[128][40];
    int i0 = blockIdx.x * 128, n0t = blockIdx.y * 128;
    int kbeg = blockIdx.z * (KDIM / 4);
    float acc[2][8][4] = {};
    mma128<KDIM>(selA ? g_XThi : g_MThi, selA ? g_XTlo : g_MTlo,
                 selB ? g_XThi : g_MThi, selB ? g_XTlo : g_MTlo,
                 i0, n0t, kbeg, kbeg + KDIM / 4, acc, sAh, sAl, sBh, sBl);
    float* C = g_part + blockIdx.z * (N0 * N0);
    EPILOGUE_LOOP({ C[(size_t)rr * N0 + cc] = a; });
}

// -- proj; modes:
//  0: G = G - M·Bop              (A-op MR)
//  1: A = M + A - M·Bop, emit XR<-A
//  2: G = A - Q1·Bop (final)     (A-op Gt = Q1 rows)
//  3: A = A·Bop (Q1), emit Gt<-Q1 rows   (A-op XR)
__global__ void __launch_bounds__(256) k_proj_mma(int mode) {
    __shared__ __align__(16) __nv_bfloat16 sAh[128][40];
    __shared__ __align__(16) __nv_bfloat16 sAl[128][40];
    __shared__ __align__(16) __nv_bfloat16 sBh[128][40];
    __shared__ __align__(16) __nv_bfloat16 sBl[128][40];
    int i0 = blockIdx.x * 128, n0t = blockIdx.y * 128;
    float acc[2][8][4] = {};
    const __nv_bfloat16 *Ah, *Al;
    if (mode == 3)      { Ah = g_XRhi; Al = g_XRlo; }
    else if (mode == 2) { Ah = g_Gthi; Al = g_Gtlo; }
    else                { Ah = g_MRhi; Al = g_MRlo; }
    mma128<N0>(Ah, Al, g_Bophi, g_Boplo, i0, n0t, 0, N0, acc, sAh, sAl, sBh, sBl);
    int lane = threadIdx.x & 31, wid = threadIdx.x >> 5;
    int wy = wid >> 1, wx = wid & 1;
    int gr = lane >> 2, lc2 = (lane & 3) * 2;
#pragma unroll
    for (int mb = 0; mb < 2; mb++)
#pragma unroll
        for (int nb = 0; nb < 8; nb++)
#pragma unroll
            for (int hf = 0; hf < 2; hf++) {
                int rr = i0 + wy * 32 + mb * 16 + gr + hf * 8;
                int cc = n0t + wx * 64 + nb * 8 + lc2;
                size_t idx = (size_t)rr * N0 + cc;
                float a0 = acc[mb][nb][hf * 2], a1 = acc[mb][nb][hf * 2 + 1];
                if (mode == 0) {
                    g_G[idx]     -= a0;
                    g_G[idx + 1] -= a1;
                } else if (mode == 1) {
                    float v0 = g_M[idx] + g_A[idx] - a0;
                    float v1 = g_M[idx + 1] + g_A[idx + 1] - a1;
                    g_A[idx] = v0; g_A[idx + 1] = v1;
                    __nv_bfloat16 h0 = __float2bfloat16(v0), h1 = __float2bfloat16(v1);
                    ((__nv_bfloat162*)g_XRhi)[idx >> 1] = __nv_bfloat162(h0, h1);
                    ((__nv_bfloat162*)g_XRlo)[idx >> 1] = __nv_bfloat162(
                        __float2bfloat16(v0 - __bfloat162float(h0)),
                        __float2bfloat16(v1 - __bfloat162float(h1)));
                } else if (mode == 3) {
                    g_A[idx] = a0; g_A[idx + 1] = a1;
                    __nv_bfloat16 h0 = __float2bfloat16(a0), h1 = __float2bfloat16(a1);
                    ((__nv_bfloat162*)g_Gthi)[idx >> 1] = __nv_bfloat162(h0, h1);
                    ((__nv_bfloat162*)g_Gtlo)[idx >> 1] = __nv_bfloat162(
                        __float2bfloat16(a0 - __bfloat162float(h0)),
                        __float2bfloat16(a1 - __bfloat162float(h1)));
                } else {
                    g_G[idx]     = g_A[idx] - a0;
                    g_G[idx + 1] = g_A[idx + 1] - a1;
                }
            }
}

// ---------------- x[i] = clip(log(|rowsumsq(G)|)/10, -1, 1) ----------------
__global__ void k_rowsq() {
    int gt = blockIdx.x * 256 + threadIdx.x;
    int row = gt >> 5, lane = gt & 31;
    const float4* rp = (const float4*)&g_G[row * N0];
    float s = 0.f;
#pragma unroll 4
    for (int c = lane; c < 128; c += 32) {
        float4 v = rp[c];
        s += v.x * v.x + v.y * v.y + v.z * v.z + v.w * v.w;
    }
#pragma unroll
    for (int o = 16; o; o >>= 1) s += __shfl_xor_sync(0xffffffffu, s, o);
    if (lane == 0) {
        float x = logf(fabsf(s)) * 0.1f;
        g_x[row] = fminf(1.0f, fmaxf(-1.0f, x));
    }
}

// ---------------- 2-layer LSTM ----------------
__global__ void k_lstm(const float* __restrict__ Lh0, const float* __restrict__ Lc0,
                       const float* __restrict__ Wih0, const float* __restrict__ Whh0,
                       const float* __restrict__ bih0, const float* __restrict__ bhh0,
                       const float* __restrict__ Wih1, const float* __restrict__ Whh1,
                       const float* __restrict__ bih1, const float* __restrict__ bhh1,
                       const float* __restrict__ Wl, const float* __restrict__ bl,
                       float* __restrict__ out) {
    __shared__ float sWih0[80], sWhh0[1600], sb0[80];
    __shared__ float sWih1[1600], sWhh1[1600], sb1[80];
    __shared__ float sWl[20], sbl[1];
    int t = threadIdx.x;
    for (int i = t; i < 80; i += 256) {
        sWih0[i] = Wih0[i];
        sb0[i] = bih0[i] + bhh0[i];
        sb1[i] = bih1[i] + bhh1[i];
    }
    for (int i = t; i < 1600; i += 256) {
        sWhh0[i] = Whh0[i];
        sWih1[i] = Wih1[i];
        sWhh1[i] = Whh1[i];
    }
    if (t < 20) sWl[t] = Wl[t];
    if (t == 0) sbl[0] = bl[0];
    __syncthreads();

    int i = blockIdx.x * 256 + t;
    float x = g_x[i];
    float h0p[20], h1p[20], h0n[20];
#pragma unroll
    for (int h = 0; h < 20; h++) {
        h0p[h] = Lh0[i * 20 + h];
        h1p[h] = Lh0[92160 + i * 20 + h];
    }
#pragma unroll
    for (int h = 0; h < 20; h++) {
        float pi = sb0[h]      + x * sWih0[h];
        float pf = sb0[20 + h] + x * sWih0[20 + h];
        float pg = sb0[40 + h] + x * sWih0[40 + h];
        float po = sb0[60 + h] + x * sWih0[60 + h];
#pragma unroll
        for (int m = 0; m < 20; m++) {
            float hm = h0p[m];
            pi += hm * sWhh0[h * 20 + m];
            pf += hm * sWhh0[(20 + h) * 20 + m];
            pg += hm * sWhh0[(40 + h) * 20 + m];
            po += hm * sWhh0[(60 + h) * 20 + m];
        }
        float c0 = Lc0[i * 20 + h];
        float c = sigf(pf) * c0 + sigf(pi) * tanhf(pg);
        float hh = sigf(po) * tanhf(c);
        h0n[h] = hh;
        out[O_H + i * 20 + h] = hh;
        out[O_C + i * 20 + h] = c;
    }
    float lacc = sbl[0];
#pragma unroll
    for (int h = 0; h < 20; h++) {
        float pi = sb1[h], pf = sb1[20 + h], pg = sb1[40 + h], po = sb1[60 + h];
#pragma unroll
        for (int m = 0; m < 20; m++) {
            float a = h0n[m], b = h1p[m];
            pi += a * sWih1[h * 20 + m]        + b * sWhh1[h * 20 + m];
            pf += a * sWih1[(20 + h) * 20 + m] + b * sWhh1[(20 + h) * 20 + m];
            pg += a * sWih1[(40 + h) * 20 + m] + b * sWhh1[(40 + h) * 20 + m];
            po += a * sWih1[(60 + h) * 20 + m] + b * sWhh1[(60 + h) * 20 + m];
        }
        float c1 = Lc0[92160 + i * 20 + h];
        float c = sigf(pf) * c1 + sigf(pi) * tanhf(pg);
        float hh = sigf(po) * tanhf(c);
        out[O_H + 92160 + i * 20 + h] = hh;
        out[O_C + 92160 + i * 20 + h] = c;
        lacc += hh * sWl[h];
    }
    g_lraw[i] = lacc * 0.1f;
}

__global__ void k_mean() {
    __shared__ float sm[256];
    int t = threadIdx.x;
    float s = 0.f;
    for (int i = t; i < KDIM; i += 256) s += g_lraw[i];
    sm[t] = s;
    __syncthreads();
    for (int o = 128; o; o >>= 1) {
        if (t < o) sm[t] += sm[t + o];
        __syncthreads();
    }
    if (t == 0) g_mean = sm[0] * (1.0f / KDIM);
}

// ---------------- L (fp32 out + split-bf16) ----------------
__global__ void k_build_L(const float4* __restrict__ Lb, float4* __restrict__ outL) {
    int gid = blockIdx.x * 256 + threadIdx.x;
    int base = gid * 4;
    int i = base / KDIM;
    int j0 = base - i * KDIM;
    float dv = g_lraw[i] - g_mean + 1.0f;
    float4 lb = Lb[gid];
    float4 r;
    r.x = fmaxf((j0 + 0 == i) ? dv : 0.0f, lb.x);
    r.y = fmaxf((j0 + 1 == i) ? dv : 0.0f, lb.y);
    r.z = fmaxf((j0 + 2 == i) ? dv : 0.0f, lb.z);
    r.w = fmaxf((j0 + 3 == i) ? dv : 0.0f, lb.w);
    outL[gid] = r;
    __nv_bfloat16 hx = __float2bfloat16(r.x), hy = __float2bfloat16(r.y);
    __nv_bfloat16 hz = __float2bfloat16(r.z), hw = __float2bfloat16(r.w);
    __nv_bfloat162* ph = (__nv_bfloat162*)g_Lhi;
    __nv_bfloat162* pl = (__nv_bfloat162*)g_Llo;
    ph[2 * gid]     = __nv_bfloat162(hx, hy);
    ph[2 * gid + 1] = __nv_bfloat162(hz, hw);
    pl[2 * gid]     = __nv_bfloat162(__float2bfloat16(r.x - __bfloat162float(hx)),
                                     __float2bfloat16(r.y - __bfloat162float(hy)));
    pl[2 * gid + 1] = __nv_bfloat162(__float2bfloat16(r.z - __bfloat162float(hz)),
                                     __float2bfloat16(r.w - __bfloat162float(hw)));
}

// -------- left-looking chol, merged factor+TRSM (2 syncs/column) --------
__global__ void k_chol_left(int p) {
    __shared__ float S1[64][65];   // D
    __shared__ float S2[64][65];   // C
    int bi = p + blockIdx.x;
    bool offd = (bi != p);
    int t = threadIdx.x, ty = t >> 4, tx = t & 15;
    float accC[4][4] = {}, accD[4][4];
#pragma unroll
    for (int u = 0; u < 4; u++)
#pragma unroll
        for (int v = 0; v < 4; v++) {
            accD[u][v] = g_S[(p * 64 + ty * 4 + u) * N0 + p * 64 + tx * 4 + v];
            if (offd)
                accC[u][v] = g_S[(bi * 64 + ty * 4 + u) * N0 + p * 64 + tx * 4 + v];
        }
    for (int kb = 0; kb < p; kb++) {
        for (int idx = t; idx < 4096; idx += 256) {
            int r = idx >> 6, c = idx & 63;
            S1[r][c] = g_S[(bi * 64 + r) * N0 + kb * 64 + c];
            S2[r][c] = g_S[(p * 64 + r) * N0 + kb * 64 + c];
        }
        __syncthreads();
#pragma unroll 8
        for (int k = 0; k < 64; k++) {
            float lb_[4], lp_[4], lpr[4];
#pragma unroll
            for (int u = 0; u < 4; u++) {
                lb_[u] = S1[ty * 4 + u][k];
                lp_[u] = S2[tx * 4 + u][k];
                lpr[u] = S2[ty * 4 + u][k];
            }
#pragma unroll
            for (int u = 0; u < 4; u++)
#pragma unroll
                for (int v = 0; v < 4; v++) {
                    accC[u][v] -= lb_[u] * lp_[v];
                    accD[u][v] -= lpr[u] * lp_[v];
                }
        }
        __syncthreads();
    }
#pragma unroll
    for (int u = 0; u < 4; u++)
#pragma unroll
        for (int v = 0; v < 4; v++) {
            S1[ty * 4 + u][tx * 4 + v] = accD[u][v];
            S2[ty * 4 + u][tx * 4 + v] = accC[u][v];
        }
    __syncthreads();
    float mydj = 0.0f;
    for (int j = 0; j < 64; j++) {
        float dj = sqrtf(fmaxf(S1[j][j], 1e-30f));
        if (t == j) mydj = dj;
        float inv = 1.0f / dj;
        for (int r = j + 1 + t; r < 64; r += 256) S1[r][j] *= inv;
        if (offd && t < 64) S2[t][j] *= inv;
        __syncthreads();
        for (int idx = t; idx < 4096; idx += 256) {
            int r = idx >> 6, c = idx & 63;
            if (c > j) {
                float dcj = S1[c][j];
                if (r >= c) S1[r][c] -= S1[r][j] * dcj;
                if (offd)   S2[r][c] -= S2[r][j] * dcj;
            }
        }
        __syncthreads();
    }
    if (t < 64) S1[t][t] = mydj;
    __syncthreads();
    if (!offd) {
        for (int idx = t; idx < 4096; idx += 256) {
            int r = idx >> 6, c = idx & 63;
            g_S[(p * 64 + r) * N0 + p * 64 + c] = S1[r][c];
        }
    } else {
        for (int idx = t; idx < 4096; idx += 256) {
            int r = idx >> 6, c = idx & 63;
            g_S[(bi * 64 + r) * N0 + p * 64 + c] = S2[r][c];
        }
    }
}

// -------- recursive-doubling triangular inverse: Linv -> g_part --------
__global__ void k_inv_diag() {
    __shared__ float S1[64][65];
    __shared__ float S2[64][65];
    int i = blockIdx.x;
    int t = threadIdx.x;
    for (int idx = t; idx < 4096; idx += 256) {
        int r = idx >> 6, c = idx & 63;
        S1[r][c] = g_S[(i * 64 + r) * N0 + i * 64 + c];
    }
    __syncthreads();
    if (t < 64) {
        int c = t;
        for (int r = 0; r < 64; r++) {
            if (r < c) { S2[r][c] = 0.0f; continue; }
            float s = (r == c) ? 1.0f : 0.0f;
            for (int k = c; k < r; k++) s -= S1[r][k] * S2[k][c];
            S2[r][c] = s / S1[r][r];
        }
    }
    __syncthreads();
    for (int idx = t; idx < 4096; idx += 256) {
        int r = idx >> 6, c = idx & 63;
        g_part[(i * 64 + r) * N0 + i * 64 + c] = S2[r][c];
    }
}

// P[r][c] = sum_{m} L[r][m] * Linv[m][c]  (block units) -> g_Sym
__global__ void k_tri_P(int h) {
    __shared__ float SA[64][65];
    __shared__ float SB[64][65];
    int hh = h * h;
    int q = blockIdx.x / hh, loc = blockIdx.x % hh;
    int ri = loc / h, ci = loc % h;
    int r = 2 * q * h + h + ri, c = 2 * q * h + ci;
    int t = threadIdx.x, ty = t >> 4, tx = t & 15;
    float acc[4][4] = {};
    for (int m = c; m < 2 * q * h + h; m++) {
        for (int idx = t; idx < 4096; idx += 256) {
            int rr = idx >> 6, cc = idx & 63;
            SA[rr][cc] = g_S[(r * 64 + rr) * N0 + m * 64 + cc];
            SB[rr][cc] = g_part[(m * 64 + rr) * N0 + c * 64 + cc];
        }
        __syncthreads();
#pragma unroll 8
        for (int k = 0; k < 64; k++)
#pragma unroll
            for (int u = 0; u < 4; u++)
#pragma unroll
                for (int v = 0; v < 4; v++)
                    acc[u][v] += SA[ty * 4 + u][k] * SB[k][tx * 4 + v];
        __syncthreads();
    }
#pragma unroll
    for (int u = 0; u < 4; u++)
#pragma unroll
        for (int v = 0; v < 4; v++)
            g_Sym[(r * 64 + ty * 4 + u) * N0 + c * 64 + tx * 4 + v] = acc[u][v];
}

// X[r][c] = -sum_{m} Linv[r][m] * P[m][c] -> g_part
__global__ void k_tri_X(int h) {
    __shared__ float SA[64][65];
    __shared__ float SB[64][65];
    int hh = h * h;
    int q = blockIdx.x / hh, loc = blockIdx.x % hh;
    int ri = loc / h, ci = loc % h;
    int r = 2 * q * h + h + ri, c = 2 * q * h + ci;
    int t = threadIdx.x, ty = t >> 4, tx = t & 15;
    float acc[4][4] = {};
    for (int m = 2 * q * h + h; m <= r; m++) {
        for (int idx = t; idx < 4096; idx += 256) {
            int rr = idx >> 6, cc = idx & 63;
            SA[rr][cc] = g_part[(r * 64 + rr) * N0 + m * 64 + cc];
            SB[rr][cc] = g_Sym[(m * 64 + rr) * N0 + c * 64 + cc];
        }
        __syncthreads();
#pragma unroll 8
        for (int k = 0; k < 64; k++)
#pragma unroll
            for (int u = 0; u < 4; u++)
#pragma unroll
                for (int v = 0; v < 4; v++)
                    acc[u][v] += SA[ty * 4 + u][k] * SB[k][tx * 4 + v];
        __syncthreads();
    }
#pragma unroll
    for (int u = 0; u < 4; u++)
#pragma unroll
        for (int v = 0; v < 4; v++)
            g_part[(r * 64 + ty * 4 + u) * N0 + c * 64 + tx * 4 + v] = -acc[u][v];
}

// ---------------- new_s = Q^T ----------------
__global__ void k_write_s(float* __restrict__ outS) {
    __shared__ float tile[32][33];
    int kB = blockIdx.x * 32, nB = blockIdx.y * 32;
    int tx = threadIdx.x, ty = threadIdx.y;
#pragma unroll
    for (int r = 0; r < 32; r += 8)
        tile[ty + r][tx] = g_G[(kB + ty + r) * N0 + nB + tx];
    __syncthreads();
#pragma unroll
    for (int r = 0; r < 32; r += 8)
        outS[(nB + ty + r) * KDIM + kB + tx] = tile[tx][ty + r];
}

extern "C" void kernel_launch(void* const* d_in, const int* in_sizes, int n_in,
                              void* d_out, int out_size) {
    const float* e    = (const float*)d_in[0];
    const float* eg   = (const float*)d_in[1];
    const float* s    = (const float*)d_in[2];
    const float* sg   = (const float*)d_in[3];
    const float* Lh0  = (const float*)d_in[4];
    const float* Lc0  = (const float*)d_in[5];
    const float* Lb   = (const float*)d_in[6];
    const float* Wih0 = (const float*)d_in[7];
    const float* Whh0 = (const float*)d_in[8];
    const float* bih0 = (const float*)d_in[9];
    const float* bhh0 = (const float*)d_in[10];
    const float* Wih1 = (const float*)d_in[11];
    const float* Whh1 = (const float*)d_in[12];
    const float* bih1 = (const float*)d_in[13];
    const float* bhh1 = (const float*)d_in[14];
    const float* Wl   = (const float*)d_in[15];
    const float* bl   = (const float*)d_in[16];
    const float* e_lr = (const float*)d_in[17];
    const float* s_lr = (const float*)d_in[18];
    float* out = (float*)d_out;

    k_update_e<<<16384, 256>>>((const float4*)e, (const float4*)eg, e_lr,
                               (float4*)(out + O_E));
    k_make_MMg<<<dim3(144, 16), dim3(32, 8)>>>(s, sg, s_lr);
    k_stsplit<<<2304, 256>>>((const float4*)s, s_lr, 0);   // M^T  -> MT
    k_stsplit<<<2304, 256>>>((const float4*)sg, s_lr, 1);  // Mg^T -> XT
    k_rsplit<<<2304, 256>>>();                             // M rows -> MR
    // Sym = sym(M^T Mg) (+Bop); G = Mg - M @ Sym
    k_gram_mma<<<dim3(4, 4, 4), 256>>>(0, 1);
    k_reduce_sym<<<512, 512>>>(0, 0);
    k_proj_mma<<<dim3(36, 4), 256>>>(0);
    // LogAndSign -> LSTM -> L
    k_rowsq<<<576, 256>>>();
    k_lstm<<<18, 256>>>(Lh0, Lc0, Wih0, Whh0, bih0, bhh0,
                        Wih1, Whh1, bih1, bhh1, Wl, bl, out);
    k_mean<<<1, 256>>>();
    k_build_L<<<20736, 256>>>((const float4*)Lb, (float4*)(out + O_L));
    // LG on tensor cores
    k_tsplit<<<dim3(144, 16), dim3(32, 8)>>>(3);           // G^T -> Gt
    k_lg_mma<<<dim3(36, 4), 256>>>();
    // A = M + LG - M @ sym(M^T LG)   (mode-1 also emits A row-splits -> XR)
    k_tsplit<<<dim3(144, 16), dim3(32, 8)>>>(1);           // LG^T -> XT
    k_gram_mma<<<dim3(4, 4, 4), 256>>>(0, 1);
    k_reduce_sym<<<512, 512>>>(0, 0);
    k_proj_mma<<<dim3(36, 4), 256>>>(1);
    // CholQR pass 1: fp32 Gram (precision-critical) -> chol (8) -> Linv -> Q1
    k_gemm_tn<<<dim3(8, 8, 4), 256>>>();
    k_reduce_sym<<<512, 512>>>(1, -1);
    for (int p = 0; p < 8; p++) k_chol_left<<<8 - p, 256>>>(p);
    k_inv_diag<<<8, 256>>>();
    for (int h = 1; h <= 4; h <<= 1) {
        int nb = (4 / h) * h * h;
        k_tri_P<<<nb, 256>>>(h);
        k_tri_X<<<nb, 256>>>(h);
    }
    k_bsplit_linv<<<512, 512>>>();
    k_proj_mma<<<dim3(36, 4), 256>>>(3);                   // Q1 (+rows -> Gt)
    // Newton (single pass): E-gram (+U), Q2 = Q1 - Q1·U  -> g_G
    k_tsplit<<<dim3(144, 16), dim3(32, 8)>>>(1);           // Q1^T -> XT
    k_gram_mma<<<dim3(4, 4, 4), 256>>>(1, 1);
    k_reduce_sym<<<512, 512>>>(0, 1);
    k_proj_mma<<<dim3(36, 4), 256>>>(2);                   // G = Q2
    // new_s
    k_write_s<<<dim3(144, 16), dim3(32, 8)>>>(out + O_S);
}